// round 3
// baseline (speedup 1.0000x reference)
#include <cuda_runtime.h>
#include <math.h>
#include <stdint.h>

// ---------------------------------------------------------------------------
// Problem sizes (fixed by the dataset)
// ---------------------------------------------------------------------------
#define NMAX 50000
#define EMAX 800000
#define ETMAX (EMAX + NMAX)

// ---------------------------------------------------------------------------
// Scratch (device globals: no allocation allowed)
// ---------------------------------------------------------------------------
__device__ int   g_csr[ETMAX];
__device__ int   g_rowptr[NMAX + 1];
__device__ int   g_cur[NMAX];
__device__ int   g_deg[NMAX];
__device__ float g_dinv[NMAX];

__device__ float g_h1[(size_t)NMAX * 256];
__device__ float g_mlp1[(size_t)NMAX * 256];
__device__ float g_x1[(size_t)NMAX * 256];
__device__ float g_es1[NMAX * 8];
__device__ float g_ed1[NMAX * 8];

__device__ float g_h2[(size_t)NMAX * 128];
__device__ float g_mlp2[(size_t)NMAX * 128];
__device__ float g_x2[(size_t)NMAX * 128];

__device__ float g_h3[(size_t)NMAX * 512];
__device__ float g_mlp3[(size_t)NMAX * 64];
__device__ float g_es3[NMAX * 8];
__device__ float g_ed3[NMAX * 8];
__device__ float g_x3[(size_t)NMAX * 64];

__device__ float g_h4[NMAX * 2];
__device__ float g_mlp4[NMAX * 2];

// ---------------------------------------------------------------------------
// Small helpers
// ---------------------------------------------------------------------------
__device__ __forceinline__ float warp_sum(float v) {
#pragma unroll
    for (int o = 16; o > 0; o >>= 1) v += __shfl_xor_sync(0xffffffffu, v, o);
    return v;
}
__device__ __forceinline__ float warp_max(float v) {
#pragma unroll
    for (int o = 16; o > 0; o >>= 1) v = fmaxf(v, __shfl_xor_sync(0xffffffffu, v, o));
    return v;
}
__device__ __forceinline__ float lrelu(float x) { return x > 0.f ? x : 0.2f * x; }

// ---------------------------------------------------------------------------
// CSR construction (deterministic: sorted adjacency lists)
// edge_index arrives as int32 (harness lowers int64 -> int32): row 0 = src,
// row 1 = dst, each of length E.
// ---------------------------------------------------------------------------
__global__ void k_init_deg(int n) {
    int i = blockIdx.x * blockDim.x + threadIdx.x;
    if (i < n) g_deg[i] = 1;  // self loop
}

__global__ void k_count(const int* __restrict__ ei, int E, int n) {
    int e = blockIdx.x * blockDim.x + threadIdx.x;
    if (e < E) {
        int d = ei[E + e];  // dst row
        if (d >= 0 && d < n) atomicAdd(&g_deg[d], 1);
    }
}

// single block of 1024 threads: exclusive scan of deg -> rowptr, cur, dinv
__global__ void k_scan(int n) {
    __shared__ int sh[1024];
    int t = threadIdx.x;
    const int CH = (n + 1023) / 1024;
    int base = t * CH;
    int s = 0;
    for (int k = 0; k < CH; k++) {
        int i = base + k;
        if (i < n) s += g_deg[i];
    }
    sh[t] = s;
    __syncthreads();
    for (int off = 1; off < 1024; off <<= 1) {
        int v = (t >= off) ? sh[t - off] : 0;
        __syncthreads();
        sh[t] += v;
        __syncthreads();
    }
    int run = sh[t] - s;  // exclusive prefix for this thread's chunk
    for (int k = 0; k < CH; k++) {
        int i = base + k;
        if (i < n) {
            g_rowptr[i] = run;
            g_cur[i] = run;
            g_dinv[i] = rsqrtf((float)g_deg[i]);
            run += g_deg[i];
        }
    }
    if (t == 0) g_rowptr[n] = sh[1023];
}

__global__ void k_scatter(const int* __restrict__ ei, int E, int n) {
    int e = blockIdx.x * blockDim.x + threadIdx.x;
    int tot = E + n;
    if (e >= tot) return;
    int s, d;
    if (e < E) {
        s = ei[e];
        d = ei[E + e];
        if (s < 0 || s >= n || d < 0 || d >= n) return;  // defensive
    } else {
        s = d = e - E;  // self loop
    }
    int pos = atomicAdd(&g_cur[d], 1);
    g_csr[pos] = s;
}

__global__ void k_sort_lists(int n) {
    int i = blockIdx.x * blockDim.x + threadIdx.x;
    if (i >= n) return;
    int s = g_rowptr[i], e = g_rowptr[i + 1];
    for (int a = s + 1; a < e; a++) {
        int v = g_csr[a];
        int b = a - 1;
        while (b >= s && g_csr[b] > v) {
            g_csr[b + 1] = g_csr[b];
            b--;
        }
        g_csr[b + 1] = v;
    }
}

// ---------------------------------------------------------------------------
// SGEMM: C[M,N] = A[M,K] @ B[K,N] (+ bias). K%16==0, N%64==0.
// Block tile 128x64, thread tile 8x4, 256 threads.
// ---------------------------------------------------------------------------
__global__ __launch_bounds__(256) void k_sgemm(
    const float* __restrict__ A, const float* __restrict__ B,
    const float* __restrict__ bias, float* __restrict__ C,
    int M, int N, int K)
{
    constexpr int BM = 128, BN = 64, BK = 16, TM = 8, TN = 4;
    __shared__ float As[BK][BM];
    __shared__ float Bs[BK][BN];

    int tid = threadIdx.x;
    int trow = tid / (BN / TN);   // 0..15
    int tcol = tid % (BN / TN);   // 0..15
    int blockRow = blockIdx.y * BM;
    int blockCol = blockIdx.x * BN;

    float acc[TM][TN];
#pragma unroll
    for (int m = 0; m < TM; m++)
#pragma unroll
        for (int n = 0; n < TN; n++) acc[m][n] = 0.f;

    int a_r = tid / 4;             // 0..63
    int a_c = (tid % 4) * 4;       // 0,4,8,12
    int b_r = tid / 16;            // 0..15
    int b_c = (tid % 16) * 4;      // 0..60

    for (int k0 = 0; k0 < K; k0 += BK) {
        // load A tile (128x16), transposed into As[k][m]
#pragma unroll
        for (int i = 0; i < BM; i += 64) {
            int r = a_r + i;
            int grow = blockRow + r;
            float4 v = make_float4(0.f, 0.f, 0.f, 0.f);
            if (grow < M) v = *(const float4*)&A[(size_t)grow * K + k0 + a_c];
            As[a_c + 0][r] = v.x;
            As[a_c + 1][r] = v.y;
            As[a_c + 2][r] = v.z;
            As[a_c + 3][r] = v.w;
        }
        // load B tile (16x64)
        {
            int br = k0 + b_r;
            float4 v = make_float4(0.f, 0.f, 0.f, 0.f);
            if (br < K) v = *(const float4*)&B[(size_t)br * N + blockCol + b_c];
            *(float4*)&Bs[b_r][b_c] = v;
        }
        __syncthreads();
#pragma unroll
        for (int k = 0; k < BK; k++) {
            float ar[TM], br[TN];
            float4 a0 = *(const float4*)&As[k][trow * TM];
            float4 a1 = *(const float4*)&As[k][trow * TM + 4];
            ar[0] = a0.x; ar[1] = a0.y; ar[2] = a0.z; ar[3] = a0.w;
            ar[4] = a1.x; ar[5] = a1.y; ar[6] = a1.z; ar[7] = a1.w;
            float4 b0 = *(const float4*)&Bs[k][tcol * TN];
            br[0] = b0.x; br[1] = b0.y; br[2] = b0.z; br[3] = b0.w;
#pragma unroll
            for (int m = 0; m < TM; m++)
#pragma unroll
                for (int n = 0; n < TN; n++) acc[m][n] += ar[m] * br[n];
        }
        __syncthreads();
    }

#pragma unroll
    for (int m = 0; m < TM; m++) {
        int grow = blockRow + trow * TM + m;
        if (grow >= M) continue;
#pragma unroll
        for (int n = 0; n < TN; n++) {
            int gcol = blockCol + tcol * TN + n;
            float v = acc[m][n];
            if (bias) v += bias[gcol];
            C[(size_t)grow * N + gcol] = v;
        }
    }
}

// ---------------------------------------------------------------------------
// Attention source/dest scores: es[i][h] = sum_c h[i][h][c]*a_s[h][c]
// ---------------------------------------------------------------------------
template <int H, int C>
__global__ __launch_bounds__(256) void k_attn_scores(
    const float* __restrict__ h, const float* __restrict__ a_s,
    const float* __restrict__ a_d, float* __restrict__ es,
    float* __restrict__ ed, int n)
{
    int node = (blockIdx.x * blockDim.x + threadIdx.x) >> 5;
    int lane = threadIdx.x & 31;
    if (node >= n) return;
    const float* row = h + (size_t)node * (H * C);
    float esl[H], edl[H];
#pragma unroll
    for (int hh = 0; hh < H; hh++) {
        float s = 0.f, d = 0.f;
#pragma unroll
        for (int c = 0; c < C; c += 32) {
            float v = row[hh * C + c + lane];
            s += v * a_s[hh * C + c + lane];
            d += v * a_d[hh * C + c + lane];
        }
        esl[hh] = warp_sum(s);
        edl[hh] = warp_sum(d);
    }
    if (lane == 0) {
#pragma unroll
        for (int hh = 0; hh < H; hh++) {
            es[node * H + hh] = esl[hh];
            ed[node * H + hh] = edl[hh];
        }
    }
}

// ---------------------------------------------------------------------------
// GAT layer 1: H=8, C=32, concat -> 256. Fused +bias +mlp +LayerNorm.
// One warp per destination node.
// ---------------------------------------------------------------------------
__global__ __launch_bounds__(256) void k_gat1_agg(
    const float* __restrict__ h1, const float* __restrict__ es,
    const float* __restrict__ ed, const float* __restrict__ gb,
    const float* __restrict__ mlp, const float* __restrict__ lnw,
    const float* __restrict__ lnb, float* __restrict__ out, int n)
{
    int node = (blockIdx.x * blockDim.x + threadIdx.x) >> 5;
    int lane = threadIdx.x & 31;
    if (node >= n) return;
    int start = g_rowptr[node], end = g_rowptr[node + 1];

    float edi[8];
#pragma unroll
    for (int h = 0; h < 8; h++) edi[h] = ed[node * 8 + h];

    // phase 1: per-head max over incoming edges
    float mx[8];
#pragma unroll
    for (int h = 0; h < 8; h++) mx[h] = -1e30f;
    for (int idx = start + lane; idx < end; idx += 32) {
        int j = g_csr[idx];
        const float4* e4 = (const float4*)(es + (size_t)j * 8);
        float4 a = e4[0], b = e4[1];
        float ev[8] = {a.x, a.y, a.z, a.w, b.x, b.y, b.z, b.w};
#pragma unroll
        for (int h = 0; h < 8; h++) mx[h] = fmaxf(mx[h], lrelu(ev[h] + edi[h]));
    }
#pragma unroll
    for (int h = 0; h < 8; h++) mx[h] = warp_max(mx[h]);

    // lane h (h<8) handles head h in the exp computation
    float mxl = mx[0], edl = edi[0];
#pragma unroll
    for (int h = 1; h < 8; h++)
        if (lane == h) { mxl = mx[h]; edl = edi[h]; }

    // phase 2: accumulate exp-weighted sums
    float acc[8], sa[8];
#pragma unroll
    for (int h = 0; h < 8; h++) { acc[h] = 0.f; sa[h] = 0.f; }

    for (int idx = start; idx < end; idx++) {
        int j = g_csr[idx];
        float exh = 0.f;
        if (lane < 8) {
            float e = lrelu(es[(size_t)j * 8 + lane] + edl);
            exh = __expf(e - mxl);
        }
        float exv[8];
#pragma unroll
        for (int h = 0; h < 8; h++) exv[h] = __shfl_sync(0xffffffffu, exh, h);
        const float* hr = h1 + (size_t)j * 256;
#pragma unroll
        for (int h = 0; h < 8; h++) {
            acc[h] += exv[h] * hr[h * 32 + lane];
            sa[h] += exv[h];
        }
    }

    // epilogue: alpha-normalize, +bias +mlp, LayerNorm(256)
    float o[8];
    const float* mr = mlp + (size_t)node * 256;
#pragma unroll
    for (int h = 0; h < 8; h++) {
        int c = h * 32 + lane;
        o[h] = acc[h] / (sa[h] + 1e-16f) + gb[c] + mr[c];
    }
    float s = 0.f;
#pragma unroll
    for (int h = 0; h < 8; h++) s += o[h];
    float mean = warp_sum(s) * (1.f / 256.f);
    float v = 0.f;
#pragma unroll
    for (int h = 0; h < 8; h++) { float d = o[h] - mean; v += d * d; }
    float inv = rsqrtf(warp_sum(v) * (1.f / 256.f) + 1e-5f);
    float* orow = out + (size_t)node * 256;
#pragma unroll
    for (int h = 0; h < 8; h++) {
        int c = h * 32 + lane;
        orow[c] = (o[h] - mean) * inv * lnw[c] + lnb[c];
    }
}

// ---------------------------------------------------------------------------
// GCN layer (C channels, fused +bias +mlp +LayerNorm). Warp per node.
// ---------------------------------------------------------------------------
template <int C>
__global__ __launch_bounds__(256) void k_gcn_agg_ln(
    const float* __restrict__ h, const float* __restrict__ gb,
    const float* __restrict__ mlp, const float* __restrict__ lnw,
    const float* __restrict__ lnb, float* __restrict__ out, int n)
{
    constexpr int PC = C / 32;
    int node = (blockIdx.x * blockDim.x + threadIdx.x) >> 5;
    int lane = threadIdx.x & 31;
    if (node >= n) return;
    int start = g_rowptr[node], end = g_rowptr[node + 1];
    float di = g_dinv[node];

    float acc[PC];
#pragma unroll
    for (int k = 0; k < PC; k++) acc[k] = 0.f;

    for (int idx = start; idx < end; idx++) {
        int j = g_csr[idx];
        float w = g_dinv[j];
        const float* hr = h + (size_t)j * C;
#pragma unroll
        for (int k = 0; k < PC; k++) acc[k] += w * hr[k * 32 + lane];
    }

    float o[PC];
    const float* mr = mlp + (size_t)node * C;
#pragma unroll
    for (int k = 0; k < PC; k++) {
        int c = k * 32 + lane;
        o[k] = di * acc[k] + gb[c] + mr[c];
    }
    float s = 0.f;
#pragma unroll
    for (int k = 0; k < PC; k++) s += o[k];
    float mean = warp_sum(s) * (1.f / C);
    float v = 0.f;
#pragma unroll
    for (int k = 0; k < PC; k++) { float d = o[k] - mean; v += d * d; }
    float inv = rsqrtf(warp_sum(v) * (1.f / C) + 1e-5f);
    float* orow = out + (size_t)node * C;
#pragma unroll
    for (int k = 0; k < PC; k++) {
        int c = k * 32 + lane;
        orow[c] = (o[k] - mean) * inv * lnw[c] + lnb[c];
    }
}

// ---------------------------------------------------------------------------
// GAT layer 3: H=8, C=64, mean over heads -> 64. Fused +bias +mlp +LN.
// ---------------------------------------------------------------------------
__global__ __launch_bounds__(256) void k_gat3_agg(
    const float* __restrict__ h3, const float* __restrict__ es,
    const float* __restrict__ ed, const float* __restrict__ gb,
    const float* __restrict__ mlp, const float* __restrict__ lnw,
    const float* __restrict__ lnb, float* __restrict__ out, int n)
{
    int node = (blockIdx.x * blockDim.x + threadIdx.x) >> 5;
    int lane = threadIdx.x & 31;
    if (node >= n) return;
    int start = g_rowptr[node], end = g_rowptr[node + 1];

    float edi[8];
#pragma unroll
    for (int h = 0; h < 8; h++) edi[h] = ed[node * 8 + h];

    float mx[8];
#pragma unroll
    for (int h = 0; h < 8; h++) mx[h] = -1e30f;
    for (int idx = start + lane; idx < end; idx += 32) {
        int j = g_csr[idx];
        const float4* e4 = (const float4*)(es + (size_t)j * 8);
        float4 a = e4[0], b = e4[1];
        float ev[8] = {a.x, a.y, a.z, a.w, b.x, b.y, b.z, b.w};
#pragma unroll
        for (int h = 0; h < 8; h++) mx[h] = fmaxf(mx[h], lrelu(ev[h] + edi[h]));
    }
#pragma unroll
    for (int h = 0; h < 8; h++) mx[h] = warp_max(mx[h]);

    float mxl = mx[0], edl = edi[0];
#pragma unroll
    for (int h = 1; h < 8; h++)
        if (lane == h) { mxl = mx[h]; edl = edi[h]; }

    float acc0[8], acc1[8], sa[8];
#pragma unroll
    for (int h = 0; h < 8; h++) { acc0[h] = 0.f; acc1[h] = 0.f; sa[h] = 0.f; }

    for (int idx = start; idx < end; idx++) {
        int j = g_csr[idx];
        float exh = 0.f;
        if (lane < 8) {
            float e = lrelu(es[(size_t)j * 8 + lane] + edl);
            exh = __expf(e - mxl);
        }
        float exv[8];
#pragma unroll
        for (int h = 0; h < 8; h++) exv[h] = __shfl_sync(0xffffffffu, exh, h);
        const float* hr = h3 + (size_t)j * 512;
#pragma unroll
        for (int h = 0; h < 8; h++) {
            acc0[h] += exv[h] * hr[h * 64 + lane];
            acc1[h] += exv[h] * hr[h * 64 + 32 + lane];
            sa[h] += exv[h];
        }
    }

    float o0 = 0.f, o1 = 0.f;
#pragma unroll
    for (int h = 0; h < 8; h++) {
        float inv = 1.f / (sa[h] + 1e-16f);
        o0 += acc0[h] * inv;
        o1 += acc1[h] * inv;
    }
    o0 *= 0.125f;
    o1 *= 0.125f;
    const float* mr = mlp + (size_t)node * 64;
    o0 += gb[lane] + mr[lane];
    o1 += gb[lane + 32] + mr[lane + 32];

    float mean = warp_sum(o0 + o1) * (1.f / 64.f);
    float d0 = o0 - mean, d1 = o1 - mean;
    float inv = rsqrtf(warp_sum(d0 * d0 + d1 * d1) * (1.f / 64.f) + 1e-5f);
    float* orow = out + (size_t)node * 64;
    orow[lane] = d0 * inv * lnw[lane] + lnb[lane];
    orow[lane + 32] = d1 * inv * lnw[lane + 32] + lnb[lane + 32];
}

// ---------------------------------------------------------------------------
// Final projections: h4 = x3 @ g4_W (no bias), mlp4 = x3 @ m4_W + m4_b
// ---------------------------------------------------------------------------
__global__ __launch_bounds__(256) void k_final_proj(
    const float* __restrict__ x3, const float* __restrict__ g4W,
    const float* __restrict__ m4W, const float* __restrict__ m4b, int n)
{
    int node = (blockIdx.x * blockDim.x + threadIdx.x) >> 5;
    int lane = threadIdx.x & 31;
    if (node >= n) return;
    float a0 = x3[(size_t)node * 64 + lane];
    float a1 = x3[(size_t)node * 64 + 32 + lane];
    float d0 = a0 * g4W[lane * 2 + 0] + a1 * g4W[(lane + 32) * 2 + 0];
    float d1 = a0 * g4W[lane * 2 + 1] + a1 * g4W[(lane + 32) * 2 + 1];
    float d2 = a0 * m4W[lane * 2 + 0] + a1 * m4W[(lane + 32) * 2 + 0];
    float d3 = a0 * m4W[lane * 2 + 1] + a1 * m4W[(lane + 32) * 2 + 1];
    d0 = warp_sum(d0);
    d1 = warp_sum(d1);
    d2 = warp_sum(d2);
    d3 = warp_sum(d3);
    if (lane == 0) {
        g_h4[node * 2 + 0] = d0;
        g_h4[node * 2 + 1] = d1;
        g_mlp4[node * 2 + 0] = d2 + m4b[0];
        g_mlp4[node * 2 + 1] = d3 + m4b[1];
    }
}

__global__ __launch_bounds__(256) void k_gcn4_agg(
    const float* __restrict__ g4b, float* __restrict__ out, int n)
{
    int node = (blockIdx.x * blockDim.x + threadIdx.x) >> 5;
    int lane = threadIdx.x & 31;
    if (node >= n) return;
    int start = g_rowptr[node], end = g_rowptr[node + 1];
    float s0 = 0.f, s1 = 0.f;
    for (int idx = start + lane; idx < end; idx += 32) {
        int j = g_csr[idx];
        float w = g_dinv[j];
        s0 += w * g_h4[j * 2 + 0];
        s1 += w * g_h4[j * 2 + 1];
    }
    s0 = warp_sum(s0);
    s1 = warp_sum(s1);
    if (lane == 0) {
        float di = g_dinv[node];
        out[node * 2 + 0] = di * s0 + g4b[0] + g_mlp4[node * 2 + 0];
        out[node * 2 + 1] = di * s1 + g4b[1] + g_mlp4[node * 2 + 1];
    }
}

// ---------------------------------------------------------------------------
// Host side
// ---------------------------------------------------------------------------
static void* sym(const void* s) {
    void* p = nullptr;
    cudaGetSymbolAddress(&p, s);
    return p;
}

extern "C" void kernel_launch(void* const* d_in, const int* in_sizes, int n_in,
                              void* d_out, int out_size) {
    const float* x       = (const float*)d_in[0];
    const int*   ei      = (const int*)d_in[1];   // int32 (harness lowers int64)
    const float* g1_W    = (const float*)d_in[2];
    const float* g1_as   = (const float*)d_in[3];
    const float* g1_ad   = (const float*)d_in[4];
    const float* g1_b    = (const float*)d_in[5];
    const float* g2_W    = (const float*)d_in[6];
    const float* g2_b    = (const float*)d_in[7];
    const float* g3_W    = (const float*)d_in[8];
    const float* g3_as   = (const float*)d_in[9];
    const float* g3_ad   = (const float*)d_in[10];
    const float* g3_b    = (const float*)d_in[11];
    const float* g4_W    = (const float*)d_in[12];
    const float* g4_b    = (const float*)d_in[13];
    const float* ln0_w   = (const float*)d_in[14];
    const float* ln0_b   = (const float*)d_in[15];
    const float* ln1_w   = (const float*)d_in[16];
    const float* ln1_b   = (const float*)d_in[17];
    const float* ln2_w   = (const float*)d_in[18];
    const float* ln2_b   = (const float*)d_in[19];
    const float* m1_W    = (const float*)d_in[20];
    const float* m1_b    = (const float*)d_in[21];
    const float* m2_W    = (const float*)d_in[22];
    const float* m2_b    = (const float*)d_in[23];
    const float* m3_W    = (const float*)d_in[24];
    const float* m3_b    = (const float*)d_in[25];
    const float* m4_W    = (const float*)d_in[26];
    const float* m4_b    = (const float*)d_in[27];

    const int N = in_sizes[0] / 1024;
    const int E = in_sizes[1] / 2;

    float* h1   = (float*)sym(g_h1);
    float* mlp1 = (float*)sym(g_mlp1);
    float* x1   = (float*)sym(g_x1);
    float* es1  = (float*)sym(g_es1);
    float* ed1  = (float*)sym(g_ed1);
    float* h2   = (float*)sym(g_h2);
    float* mlp2 = (float*)sym(g_mlp2);
    float* x2   = (float*)sym(g_x2);
    float* h3   = (float*)sym(g_h3);
    float* mlp3 = (float*)sym(g_mlp3);
    float* es3  = (float*)sym(g_es3);
    float* ed3  = (float*)sym(g_ed3);
    float* x3   = (float*)sym(g_x3);
    float* out  = (float*)d_out;

    const int TPB = 256;
    const int nodeBlocks = (N + 7) / 8;  // warp per node, 8 warps/block

    // --- CSR build ---
    k_init_deg<<<(N + TPB - 1) / TPB, TPB>>>(N);
    k_count<<<(E + TPB - 1) / TPB, TPB>>>(ei, E, N);
    k_scan<<<1, 1024>>>(N);
    k_scatter<<<(E + N + TPB - 1) / TPB, TPB>>>(ei, E, N);
    k_sort_lists<<<(N + TPB - 1) / TPB, TPB>>>(N);

    // --- layer 1: GAT(1024->8x32 concat 256) + MLP residual + LN ---
    {
        dim3 grid(256 / 64, (N + 127) / 128);
        k_sgemm<<<grid, 256>>>(x, g1_W, nullptr, h1, N, 256, 1024);
        k_sgemm<<<grid, 256>>>(x, m1_W, m1_b, mlp1, N, 256, 1024);
    }
    k_attn_scores<8, 32><<<nodeBlocks, TPB>>>(h1, g1_as, g1_ad, es1, ed1, N);
    k_gat1_agg<<<nodeBlocks, TPB>>>(h1, es1, ed1, g1_b, mlp1, ln0_w, ln0_b, x1, N);

    // --- layer 2: GCN(256->128) + MLP residual + LN ---
    {
        dim3 grid(128 / 64, (N + 127) / 128);
        k_sgemm<<<grid, 256>>>(x1, g2_W, nullptr, h2, N, 128, 256);
        k_sgemm<<<grid, 256>>>(x1, m2_W, m2_b, mlp2, N, 128, 256);
    }
    k_gcn_agg_ln<128><<<nodeBlocks, TPB>>>(h2, g2_b, mlp2, ln1_w, ln1_b, x2, N);

    // --- layer 3: GAT(128->8x64 mean 64) + MLP residual + LN ---
    {
        dim3 grid(512 / 64, (N + 127) / 128);
        k_sgemm<<<grid, 256>>>(x2, g3_W, nullptr, h3, N, 512, 128);
    }
    {
        dim3 grid(64 / 64, (N + 127) / 128);
        k_sgemm<<<grid, 256>>>(x2, m3_W, m3_b, mlp3, N, 64, 128);
    }
    k_attn_scores<8, 64><<<nodeBlocks, TPB>>>(h3, g3_as, g3_ad, es3, ed3, N);
    k_gat3_agg<<<nodeBlocks, TPB>>>(h3, es3, ed3, g3_b, mlp3, ln2_w, ln2_b, x3, N);

    // --- layer 4: GCN(64->2) + MLP residual ---
    k_final_proj<<<nodeBlocks, TPB>>>(x3, g4_W, m4_W, m4_b, N);
    k_gcn4_agg<<<nodeBlocks, TPB>>>(g4_b, out, N);
}